// round 4
// baseline (speedup 1.0000x reference)
#include <cuda_runtime.h>

#define T_STEPS 2000
#define HID 51
#define G4 204      // 4*HID gate rows
#define NROWS 208   // gate rows + 4 LSTM2 input-projection rows
#define FEAT 49     // 7*7
#define NTHR 224

typedef unsigned long long ull;

__device__ __forceinline__ float sigm(float x) {
    return __fdividef(1.0f, 1.0f + __expf(-x));
}
__device__ __forceinline__ float ftanh(float x) {
    return __fdividef(2.0f, 1.0f + __expf(-2.0f * x)) - 1.0f;
}

__device__ __forceinline__ ull pk(float a, float b) {
    ull r;
    asm("mov.b64 %0, {%1, %2};" : "=l"(r) : "f"(a), "f"(b));
    return r;
}
__device__ __forceinline__ ull fma2(ull a, ull b, ull c) {
    ull d;
    asm("fma.rn.f32x2 %0, %1, %2, %3;" : "=l"(d) : "l"(a), "l"(b), "l"(c));
    return d;
}
__device__ __forceinline__ ull add2(ull a, ull b) {
    ull d;
    asm("add.rn.f32x2 %0, %1, %2;" : "=l"(d) : "l"(a), "l"(b));
    return d;
}
__device__ __forceinline__ void upk(ull v, float& a, float& b) {
    asm("mov.b64 {%0, %1}, %2;" : "=f"(a), "=f"(b) : "l"(v));
}

__global__ __launch_bounds__(NTHR, 2)
void lstm_seq_kernel(const float* __restrict__ stim,
                     const float* __restrict__ Wl,   const float* __restrict__ bl,
                     const float* __restrict__ Wih1, const float* __restrict__ Whh1,
                     const float* __restrict__ bih1, const float* __restrict__ bhh1,
                     const float* __restrict__ Wih2, const float* __restrict__ Whh2,
                     const float* __restrict__ bih2, const float* __restrict__ bhh2,
                     const float* __restrict__ Wa,   const float* __restrict__ ba,
                     float* __restrict__ out)
{
    __shared__ float xlin[T_STEPS];                    // 8000 B
    __shared__ __align__(16) float h1_sh[52];          // [51] stays 0 (pad)
    __shared__ float act_sh[NROWS];
    __shared__ float wl_sh[FEAT];

    const int tid  = threadIdx.x;
    const int lane = tid & 31;
    const int wid  = tid >> 5;
    const int n    = blockIdx.x;

    if (tid < FEAT) wl_sh[tid] = Wl[tid];
    if (tid < 52)   h1_sh[tid] = 0.0f;
    __syncthreads();

    // ---- Phase 0: x_lin = relu(stim . Wl + bl), warp-per-timestep (7 warps) ----
    {
        const float blv = bl[0];
        const float* sb = stim + (size_t)n * T_STEPS * FEAT;
        for (int t = wid; t < T_STEPS; t += 7) {
            const float* p = sb + t * FEAT;
            float s = 0.0f;
            if (lane < FEAT)      s  = p[lane]      * wl_sh[lane];
            if (lane + 32 < FEAT) s += p[lane + 32] * wl_sh[lane + 32];
            #pragma unroll
            for (int off = 16; off; off >>= 1)
                s += __shfl_xor_sync(0xffffffffu, s, off);
            if (lane == 0) xlin[t] = fmaxf(s + blv, 0.0f);
        }
    }

    // ---- Per-thread static weights ----
    // Rows 0..203: Whh1 row (gates).  Rows 204..207: Wih2 row (LSTM2 input proj).
    ull   wp[26];
    float wih = 0.0f, bias = 0.0f;
    int   sel = 0;
    if (tid < NROWS) {
        const float* wr;
        if (tid < G4) {
            wr   = Whh1 + tid * HID;
            wih  = Wih1[tid];
            bias = bih1[tid] + bhh1[tid];
        } else {
            int k = tid - G4;
            wr   = Wih2 + k * HID;
            wih  = 0.0f;
            bias = bih2[k] + bhh2[k];
        }
        #pragma unroll
        for (int j = 0; j < 25; j++) wp[j] = pk(wr[2 * j], wr[2 * j + 1]);
        wp[25] = pk(wr[50], 0.0f);
        sel = tid / HID;                  // 0:i 1:f 2:g 3:o 4:raw(p-row)
    }

    // Thread 208: serial LSTM2 state + weights.
    float h2 = 0.0f, c2 = 0.0f;
    float whh2r[4], wav = 0.0f, bav = 0.0f;
    if (tid == NROWS) {
        #pragma unroll
        for (int k = 0; k < 4; k++) whh2r[k] = Whh2[k];
        wav = Wa[0];
        bav = ba[0];
    }

    float c1 = 0.0f;
    float* outp = out + (size_t)n * T_STEPS;
    __syncthreads();

    const float4* h4 = reinterpret_cast<const float4*>(h1_sh);

    // ---- Recurrence: T+1 iterations ----
    // Iter t, phase 1: rows 0..203 compute gates(t) from h1(t-1);
    //                  rows 204..207 compute p(t-1) = Wih2 . h1(t-1).
    //         phase 2: threads 0..50 update h1/c1 -> h1(t);
    //                  thread 208 runs serial LSTM2 step t-1 and writes out[t-1].
    for (int t = 0; t <= T_STEPS; t++) {
        if (tid < NROWS && (tid >= G4 || t < T_STEPS)) {
            float x = (tid < G4) ? xlin[t] : 0.0f;
            ull a0 = pk(0.0f, 0.0f), a1 = a0, a2 = a0, a3 = a0;
            #pragma unroll
            for (int q = 0; q < 13; q += 2) {
                float4 hv = h4[q];
                a0 = fma2(pk(hv.x, hv.y), wp[2 * q],     a0);
                a1 = fma2(pk(hv.z, hv.w), wp[2 * q + 1], a1);
                if (q + 1 < 13) {
                    float4 hw = h4[q + 1];
                    a2 = fma2(pk(hw.x, hw.y), wp[2 * q + 2], a2);
                    a3 = fma2(pk(hw.z, hw.w), wp[2 * q + 3], a3);
                }
            }
            a0 = add2(a0, a1);
            a2 = add2(a2, a3);
            a0 = add2(a0, a2);
            float lo, hi;
            upk(a0, lo, hi);
            float acc = (lo + hi) + (bias + x * wih);
            float v;
            if (sel == 2)      v = ftanh(acc);
            else if (sel == 4) v = acc;            // raw p-row
            else               v = sigm(acc);
            act_sh[tid] = v;
        }
        __syncthreads();

        if (t < T_STEPS && tid < HID) {
            float gi = act_sh[tid];
            float gf = act_sh[HID + tid];
            float gg = act_sh[2 * HID + tid];
            float go = act_sh[3 * HID + tid];
            c1 = gf * c1 + gi * gg;
            h1_sh[tid] = go * ftanh(c1);
        } else if (tid == NROWS && t > 0) {
            // Serial LSTM2 for step t-1 (p values from this iteration's phase 1).
            float gi = sigm (act_sh[G4 + 0] + h2 * whh2r[0]);
            float gf = sigm (act_sh[G4 + 1] + h2 * whh2r[1]);
            float gg = ftanh(act_sh[G4 + 2] + h2 * whh2r[2]);
            float go = sigm (act_sh[G4 + 3] + h2 * whh2r[3]);
            c2 = gf * c2 + gi * gg;
            h2 = go * ftanh(c2);
            outp[t - 1] = h2 * wav + bav;
        }
        __syncthreads();
    }
}

extern "C" void kernel_launch(void* const* d_in, const int* in_sizes, int n_in,
                              void* d_out, int out_size) {
    const float* stim = (const float*)d_in[0];
    const float* Wl   = (const float*)d_in[1];
    const float* bl   = (const float*)d_in[2];
    const float* Wih1 = (const float*)d_in[3];
    const float* Whh1 = (const float*)d_in[4];
    const float* bih1 = (const float*)d_in[5];
    const float* bhh1 = (const float*)d_in[6];
    const float* Wih2 = (const float*)d_in[7];
    const float* Whh2 = (const float*)d_in[8];
    const float* bih2 = (const float*)d_in[9];
    const float* bhh2 = (const float*)d_in[10];
    const float* Wa   = (const float*)d_in[11];
    const float* ba   = (const float*)d_in[12];

    const int N = out_size / T_STEPS;   // 256
    lstm_seq_kernel<<<N, NTHR>>>(stim, Wl, bl, Wih1, Whh1, bih1, bhh1,
                                 Wih2, Whh2, bih2, bhh2, Wa, ba,
                                 (float*)d_out);
}